// round 4
// baseline (speedup 1.0000x reference)
#include <cuda_runtime.h>
#include <cuda_fp16.h>
#include <cuda_fp8.h>

#define N_SEL   8192
#define N_FEAT  256
#define K_SUB   256
#define N_PERS  4
#define E_FULL  262144
#define E_RAW   262144
#define N_TOTAL 8192
#define EPSILON 0.5f
#define SCREEN  0.35f
#define LAMB1   0.5f

#define MAIN_BLOCKS 592           // 4 per SM (148 SMs)
#define COMP_BLOCKS 148           // bid < 148 -> compute (1 per SM)
#define FILL_BLOCKS (MAIN_BLOCKS - COMP_BLOCKS)   // 444
#define W_COMPUTE   (COMP_BLOCKS * 8)             // 1184 compute warps
#define OUT_F4      16777216      // 8192*8192/4

// ---------------- device scratch (no allocations allowed) ----------------
__device__ unsigned     g_qx[N_SEL * 64];         // fp8(e4m3) x, 256 B/row
__device__ __half       g_w2h[N_PERS * N_FEAT];   // metric_weight^2 in fp16
__device__ float4       g_rinv4[N_SEL];           // per-node {rinv_p0..p3}
__device__ float        g_nodew[N_SEL];           // score[batch[i]] * LAMB1
__device__ unsigned     g_bitmap[(size_t)N_SEL * N_SEL / 32];  // dedup (lazily cleared)
__device__ int          g_nhits;
__device__ int          g_hit_off[E_FULL];
__device__ float        g_hit_val[E_FULL];
__device__ int          g_hit_word[E_FULL];

// ---------------- prep 1: score norm (deterministic), nodew, w2h, reset ----------------
__global__ void prep_score_kernel(const float* __restrict__ sc,
                                  const int* __restrict__ belong,
                                  const int* __restrict__ batch,
                                  const float* __restrict__ mw) {
    __shared__ float s_sc[K_SUB];
    __shared__ int   s_bl[K_SUB];
    __shared__ float s_sum[K_SUB];
    __shared__ float s_norm[K_SUB];
    int t = threadIdx.x;
    s_sc[t] = sc[t];
    s_bl[t] = belong[t];
    __syncthreads();
    float s = 0.f;
    #pragma unroll 8
    for (int k = 0; k < K_SUB; k++)
        s += (s_bl[k] == t) ? s_sc[k] : 0.f;
    s_sum[t] = s;
    __syncthreads();
    float ns = s_sc[t] / s_sum[s_bl[t]];
    s_norm[t] = ns;
    if (t == 0) g_nhits = 0;
    __syncthreads();
    for (int i = t; i < N_SEL; i += K_SUB)
        g_nodew[i] = s_norm[batch[i]] * LAMB1;
    for (int i = t; i < N_PERS * N_FEAT; i += K_SUB) {
        float v = mw[i];
        g_w2h[i] = __float2half(v * v);
    }
}

// ---------------- prep 2: per-node rinv + fp8 quantization (warp per node) ----------------
__device__ __forceinline__ unsigned enc4(float4 v) {
    unsigned b0 = __nv_cvt_float_to_fp8(v.x, __NV_SATFINITE, __NV_E4M3);
    unsigned b1 = __nv_cvt_float_to_fp8(v.y, __NV_SATFINITE, __NV_E4M3);
    unsigned b2 = __nv_cvt_float_to_fp8(v.z, __NV_SATFINITE, __NV_E4M3);
    unsigned b3 = __nv_cvt_float_to_fp8(v.w, __NV_SATFINITE, __NV_E4M3);
    return b0 | (b1 << 8) | (b2 << 16) | (b3 << 24);
}

__global__ void __launch_bounds__(256) prep_quant_kernel(const float* __restrict__ x,
                                                         const float* __restrict__ mw) {
    int lane = threadIdx.x & 31;
    const float4* mw4 = reinterpret_cast<const float4*>(mw);
    float4 w0[N_PERS], w1[N_PERS];
    #pragma unroll
    for (int p = 0; p < N_PERS; p++) {
        float4 a = __ldg(mw4 + p * 64 + lane);
        float4 b = __ldg(mw4 + p * 64 + 32 + lane);
        w0[p] = make_float4(a.x * a.x, a.y * a.y, a.z * a.z, a.w * a.w);
        w1[p] = make_float4(b.x * b.x, b.y * b.y, b.z * b.z, b.w * b.w);
    }

    int n = (blockIdx.x * blockDim.x + threadIdx.x) >> 5;

    const float4* xr = reinterpret_cast<const float4*>(x + (size_t)n * N_FEAT);
    float4 a0 = __ldg(xr + lane);        // dims 4*lane .. 4*lane+3
    float4 a1 = __ldg(xr + lane + 32);   // dims 128+4*lane ..

    // quantize row (byte d = dim d)
    g_qx[n * 64 + lane]      = enc4(a0);
    g_qx[n * 64 + 32 + lane] = enc4(a1);

    float s0 = a0.x * a0.x, s1 = a0.y * a0.y, s2 = a0.z * a0.z, s3 = a0.w * a0.w;
    float s4 = a1.x * a1.x, s5 = a1.y * a1.y, s6 = a1.z * a1.z, s7 = a1.w * a1.w;

    float acc[N_PERS];
    #pragma unroll
    for (int p = 0; p < N_PERS; p++)
        acc[p] = s0 * w0[p].x + s1 * w0[p].y + s2 * w0[p].z + s3 * w0[p].w
               + s4 * w1[p].x + s5 * w1[p].y + s6 * w1[p].z + s7 * w1[p].w;
    #pragma unroll
    for (int p = 0; p < N_PERS; p++)
        #pragma unroll
        for (int o = 16; o > 0; o >>= 1)
            acc[p] += __shfl_xor_sync(0xffffffffu, acc[p], o);

    if (lane == 0)
        g_rinv4[n] = make_float4(1.0f / (sqrtf(acc[0]) + 1e-12f),
                                 1.0f / (sqrtf(acc[1]) + 1e-12f),
                                 1.0f / (sqrtf(acc[2]) + 1e-12f),
                                 1.0f / (sqrtf(acc[3]) + 1e-12f));
}

// ---------------- rare exact path: fp32 recompute + dedup + hit record ----------------
__device__ __noinline__ void exact_edge(int i, int j, int lane,
                                        const float* __restrict__ x,
                                        const float* __restrict__ mw,
                                        const int* __restrict__ smap) {
    const float4* xi = reinterpret_cast<const float4*>(x + (size_t)i * N_FEAT);
    const float4* xj = reinterpret_cast<const float4*>(x + (size_t)j * N_FEAT);
    float4 a0 = __ldg(xi + lane), a1 = __ldg(xi + lane + 32);
    float4 b0 = __ldg(xj + lane), b1 = __ldg(xj + lane + 32);
    float p0 = a0.x * b0.x, p1 = a0.y * b0.y, p2 = a0.z * b0.z, p3 = a0.w * b0.w;
    float p4 = a1.x * b1.x, p5 = a1.y * b1.y, p6 = a1.z * b1.z, p7 = a1.w * b1.w;

    const float4* mw4 = reinterpret_cast<const float4*>(mw);
    float f[N_PERS];
    #pragma unroll
    for (int p = 0; p < N_PERS; p++) {
        float4 wa = __ldg(mw4 + p * 64 + lane);
        float4 wb = __ldg(mw4 + p * 64 + 32 + lane);
        f[p] = p0 * wa.x * wa.x + p1 * wa.y * wa.y + p2 * wa.z * wa.z + p3 * wa.w * wa.w
             + p4 * wb.x * wb.x + p5 * wb.y * wb.y + p6 * wb.z * wb.z + p7 * wb.w * wb.w;
    }
    #pragma unroll
    for (int p = 0; p < N_PERS; p++)
        #pragma unroll
        for (int o = 16; o > 0; o >>= 1)
            f[p] += __shfl_xor_sync(0xffffffffu, f[p], o);

    if (lane == 0) {
        float4 ri = g_rinv4[i];
        float4 rj = g_rinv4[j];
        float sim = 0.25f * (f[0] * ri.x * rj.x + f[1] * ri.y * rj.y
                           + f[2] * ri.z * rj.z + f[3] * ri.w * rj.w);
        if (sim > EPSILON) {
            size_t idx = (size_t)i * N_SEL + j;
            unsigned bit = 1u << (idx & 31u);
            int word = (int)(idx >> 5);
            unsigned old = atomicOr(&g_bitmap[word], bit);
            if (!(old & bit)) {
                int slot = atomicAdd(&g_nhits, 1);
                g_hit_off[slot]  = __ldg(smap + i) * N_TOTAL + __ldg(smap + j);
                g_hit_val[slot]  = sim * g_nodew[i];
                g_hit_word[slot] = word;
            }
        }
    }
}

// ---------------- fp8 screen for one edge (warp-collective) ----------------
__device__ __forceinline__ void dec4(unsigned u, __half* h) {
    h[0] = __half(__nv_cvt_fp8_to_halfraw((__nv_fp8_storage_t)(u & 0xff), __NV_E4M3));
    h[1] = __half(__nv_cvt_fp8_to_halfraw((__nv_fp8_storage_t)((u >> 8) & 0xff), __NV_E4M3));
    h[2] = __half(__nv_cvt_fp8_to_halfraw((__nv_fp8_storage_t)((u >> 16) & 0xff), __NV_E4M3));
    h[3] = __half(__nv_cvt_fp8_to_halfraw((__nv_fp8_storage_t)(u >> 24), __NV_E4M3));
}

__device__ __forceinline__ void screen_edge(int i, int j, int lane,
                                            uint2 qi, uint2 qj,
                                            const __half2 w2r[4][4],
                                            const float* __restrict__ x,
                                            const float* __restrict__ mw,
                                            const int* __restrict__ smap) {
    __half hi[8], hj[8];
    dec4(qi.x, hi); dec4(qi.y, hi + 4);
    dec4(qj.x, hj); dec4(qj.y, hj + 4);

    __half2 acc0 = __float2half2_rn(0.f), acc1 = acc0, acc2 = acc0, acc3 = acc0;
    #pragma unroll
    for (int k = 0; k < 4; k++) {
        __half2 pr = __hmul2(__halves2half2(hi[2 * k], hi[2 * k + 1]),
                             __halves2half2(hj[2 * k], hj[2 * k + 1]));
        acc0 = __hfma2(pr, w2r[0][k], acc0);
        acc1 = __hfma2(pr, w2r[1][k], acc1);
        acc2 = __hfma2(pr, w2r[2][k], acc2);
        acc3 = __hfma2(pr, w2r[3][k], acc3);
    }
    float f0 = __low2float(acc0) + __high2float(acc0);
    float f1 = __low2float(acc1) + __high2float(acc1);
    float f2 = __low2float(acc2) + __high2float(acc2);
    float f3 = __low2float(acc3) + __high2float(acc3);

    // 6-shuffle multi-value reduction -> lane class c=lane&3 holds total of acc_c
    bool o1 = lane & 1;
    float u0 = o1 ? f0 : f1;
    float v0 = (o1 ? f1 : f0) + __shfl_xor_sync(0xffffffffu, u0, 1);
    float u1 = o1 ? f2 : f3;
    float v1 = (o1 ? f3 : f2) + __shfl_xor_sync(0xffffffffu, u1, 1);
    bool o2 = lane & 2;
    float tt = o2 ? v0 : v1;
    float w  = (o2 ? v1 : v0) + __shfl_xor_sync(0xffffffffu, tt, 2);
    w += __shfl_xor_sync(0xffffffffu, w, 4);
    w += __shfl_xor_sync(0xffffffffu, w, 8);
    w += __shfl_xor_sync(0xffffffffu, w, 16);

    int c = lane & 3;
    float ri = __ldg(reinterpret_cast<const float*>(g_rinv4) + 4 * i + c);
    float rj = __ldg(reinterpret_cast<const float*>(g_rinv4) + 4 * j + c);
    float s = w * ri * rj;
    s += __shfl_xor_sync(0xffffffffu, s, 1);
    s += __shfl_xor_sync(0xffffffffu, s, 2);
    float simA = 0.25f * __shfl_sync(0xffffffffu, s, 0);

    if (simA > SCREEN && i != j)
        exact_edge(i, j, lane, x, mw, smap);   // warp-uniform
}

// ---------------- main kernel: 148 compute blocks + 444 fill blocks ----------------
__global__ void __launch_bounds__(256) main_kernel(const float* __restrict__ x,
                                                   const float* __restrict__ mw,
                                                   const int* __restrict__ fe,
                                                   const int* __restrict__ smap,
                                                   float4* __restrict__ out4) {
    int bid = blockIdx.x;
    int tid = threadIdx.x;

    if (bid >= COMP_BLOCKS) {
        // ---- fill: streaming zero of 256 MB output ----
        float4 z = make_float4(0.f, 0.f, 0.f, 0.f);
        for (int i = (bid - COMP_BLOCKS) * 256 + tid; i < OUT_F4; i += FILL_BLOCKS * 256)
            __stcs(out4 + i, z);
        return;
    }

    // ---- compute: fp8 screening over all edges ----
    int lane = tid & 31;
    __half2 w2r[4][4];
    const __half2* w2h2 = reinterpret_cast<const __half2*>(g_w2h);
    #pragma unroll
    for (int p = 0; p < 4; p++)
        #pragma unroll
        for (int k = 0; k < 4; k++)
            w2r[p][k] = w2h2[p * 128 + lane * 4 + k];

    const uint2* qx2 = reinterpret_cast<const uint2*>(g_qx);
    int warp = bid * 8 + (tid >> 5);      // 0..1183

    for (int e = warp; e < E_FULL; e += 2 * W_COMPUTE) {
        int e2 = e + W_COMPUTE;
        bool has2 = e2 < E_FULL;
        int i1 = __ldg(fe + e);
        int j1 = __ldg(fe + E_FULL + e);
        int i2 = has2 ? __ldg(fe + e2) : i1;
        int j2 = has2 ? __ldg(fe + E_FULL + e2) : j1;

        uint2 qi1 = __ldg(qx2 + i1 * 32 + lane);
        uint2 qj1 = __ldg(qx2 + j1 * 32 + lane);
        uint2 qi2 = __ldg(qx2 + i2 * 32 + lane);
        uint2 qj2 = __ldg(qx2 + j2 * 32 + lane);

        screen_edge(i1, j1, lane, qi1, qj1, w2r, x, mw, smap);
        if (has2)
            screen_edge(i2, j2, lane, qi2, qj2, w2r, x, mw, smap);
    }
}

// ---------------- scatter: raw edges + hits + lazy bitmap clear ----------------
__global__ void scatter_kernel(const int* __restrict__ re, float* __restrict__ out) {
    int t = blockIdx.x * blockDim.x + threadIdx.x;   // exactly E_RAW threads
    int r = __ldg(re + t);
    int c = __ldg(re + E_RAW + t);
    atomicAdd(out + (size_t)r * N_TOTAL + c, 1.0f - LAMB1);
    if (t < g_nhits) {
        atomicAdd(out + (size_t)g_hit_off[t], g_hit_val[t]);
        g_bitmap[g_hit_word[t]] = 0;                 // keep replay-deterministic
    }
}

// ---------------- launch ----------------
extern "C" void kernel_launch(void* const* d_in, const int* in_sizes, int n_in,
                              void* d_out, int out_size) {
    const float* x      = (const float*)d_in[0];   // [8192, 256]
    const float* mw     = (const float*)d_in[1];   // [4, 256]
    const int*   batch  = (const int*)  d_in[2];   // [8192]
    const int*   smap   = (const int*)  d_in[3];   // [8192]
    const int*   belong = (const int*)  d_in[4];   // [256]
    const float* score  = (const float*)d_in[5];   // [256]
    const int*   fe     = (const int*)  d_in[6];   // [2, 262144]
    const int*   re     = (const int*)  d_in[7];   // [2, 262144]
    float* out = (float*)d_out;                    // [8192, 8192]

    prep_score_kernel<<<1, 256>>>(score, belong, batch, mw);
    prep_quant_kernel<<<1024, 256>>>(x, mw);
    main_kernel<<<MAIN_BLOCKS, 256>>>(x, mw, fe, smap,
                                      reinterpret_cast<float4*>(out));
    scatter_kernel<<<E_RAW / 256, 256>>>(re, out);
}

// round 5
// speedup vs baseline: 1.9338x; 1.9338x over previous
#include <cuda_runtime.h>
#include <cuda_bf16.h>

#define N_SEL   8192
#define N_FEAT  256
#define K_SUB   256
#define N_PERS  4
#define E_FULL  262144
#define E_RAW   262144
#define N_TOTAL 8192
#define EPSILON 0.5f
#define SCREEN  0.45f
#define LAMB1   0.5f

#define MAIN_BLOCKS 592                 // 4 per SM * 148 SMs (fully resident)
#define NT          (MAIN_BLOCKS * 256) // 151552 threads
#define NWARP       (NT / 32)           // 4736 warps
#define MAIN_ITERS  56                  // 56*2*NT >= 16777216 ; 56*NWARP >= E_FULL
#define OUT_F4      16777216            // 8192*8192/4

// ---------------- device scratch (no device allocations allowed) ----------------
__device__ uint4    g_qx[N_SEL * 2];      // placeholder sizing below (see real decl)
// real table: 8192 rows * 32 uint4 (512 B/row of bf16)
__device__ uint4    g_qtab[N_SEL * 32];
__device__ float4   g_rinv4[N_SEL];       // per-node {rinv_p0..p3}
__device__ float    g_nodew[N_SEL];       // score[batch[i]] * LAMB1
__device__ unsigned g_bitmap[(size_t)N_SEL * N_SEL / 32];  // dedup, lazily cleared
__device__ int      g_nhits;
__device__ int      g_hit_off[E_FULL];
__device__ float    g_hit_val[E_FULL];
__device__ int      g_hit_word[E_FULL];

// ---------------- helpers ----------------
__device__ __forceinline__ unsigned pack_bf2(float a, float b) {
    __nv_bfloat162 h = __floats2bfloat162_rn(a, b);   // low = a, high = b
    return *reinterpret_cast<unsigned*>(&h);
}
__device__ __forceinline__ void exp_bf2(unsigned u, float& lo, float& hi) {
    lo = __uint_as_float(u << 16);                    // exact bf16 -> fp32
    hi = __uint_as_float(u & 0xffff0000u);
}

// ---------------- prep: quant + rinv (blocks 0..1023) | score/nodew (block 1024) ----
__global__ void __launch_bounds__(256) prep_kernel(const float* __restrict__ x,
                                                   const float* __restrict__ mw,
                                                   const float* __restrict__ sc,
                                                   const int* __restrict__ belong,
                                                   const int* __restrict__ batch) {
    if (blockIdx.x == 1024) {
        // ---- score normalization + per-node weight ----
        __shared__ float s_sc[K_SUB];
        __shared__ int   s_bl[K_SUB];
        __shared__ float s_sum[K_SUB];
        __shared__ float s_norm[K_SUB];
        int t = threadIdx.x;
        s_sc[t] = sc[t];
        s_bl[t] = belong[t];
        __syncthreads();
        float s = 0.f;
        #pragma unroll 8
        for (int k = 0; k < K_SUB; k++)
            s += (s_bl[k] == t) ? s_sc[k] : 0.f;
        s_sum[t] = s;
        __syncthreads();
        s_norm[t] = s_sc[t] / s_sum[s_bl[t]];
        if (t == 0) g_nhits = 0;
        __syncthreads();
        for (int i = t; i < N_SEL; i += K_SUB)
            g_nodew[i] = s_norm[batch[i]] * LAMB1;
        return;
    }

    // ---- per-node: bf16 quant row + 4 inverse weighted norms (warp per node) ----
    int lane = threadIdx.x & 31;
    int n = (blockIdx.x * blockDim.x + threadIdx.x) >> 5;

    // this lane owns dims [8*lane, 8*lane+8)
    const float4* xr = reinterpret_cast<const float4*>(x + (size_t)n * N_FEAT);
    float4 a = __ldg(xr + 2 * lane);
    float4 b = __ldg(xr + 2 * lane + 1);

    g_qtab[n * 32 + lane] = make_uint4(pack_bf2(a.x, a.y), pack_bf2(a.z, a.w),
                                       pack_bf2(b.x, b.y), pack_bf2(b.z, b.w));

    float sq[8] = {a.x * a.x, a.y * a.y, a.z * a.z, a.w * a.w,
                   b.x * b.x, b.y * b.y, b.z * b.z, b.w * b.w};

    float acc[N_PERS];
    #pragma unroll
    for (int p = 0; p < N_PERS; p++) {
        const float* wp = mw + p * N_FEAT + 8 * lane;
        float t0 = 0.f;
        #pragma unroll
        for (int k = 0; k < 8; k++) {
            float w = __ldg(wp + k);
            t0 += sq[k] * w * w;
        }
        acc[p] = t0;
    }
    #pragma unroll
    for (int p = 0; p < N_PERS; p++)
        #pragma unroll
        for (int o = 16; o > 0; o >>= 1)
            acc[p] += __shfl_xor_sync(0xffffffffu, acc[p], o);

    if (lane == 0)
        g_rinv4[n] = make_float4(1.0f / (sqrtf(acc[0]) + 1e-12f),
                                 1.0f / (sqrtf(acc[1]) + 1e-12f),
                                 1.0f / (sqrtf(acc[2]) + 1e-12f),
                                 1.0f / (sqrtf(acc[3]) + 1e-12f));
}

// ---------------- rare exact path: fp32 recompute + dedup + hit record ----------------
__device__ __noinline__ void exact_edge(int i, int j, int lane,
                                        const float* __restrict__ x,
                                        const float* __restrict__ mw,
                                        const int* __restrict__ smap) {
    const float4* xi = reinterpret_cast<const float4*>(x + (size_t)i * N_FEAT);
    const float4* xj = reinterpret_cast<const float4*>(x + (size_t)j * N_FEAT);
    float4 a0 = __ldg(xi + 2 * lane), a1 = __ldg(xi + 2 * lane + 1);
    float4 b0 = __ldg(xj + 2 * lane), b1 = __ldg(xj + 2 * lane + 1);
    float pr[8] = {a0.x * b0.x, a0.y * b0.y, a0.z * b0.z, a0.w * b0.w,
                   a1.x * b1.x, a1.y * b1.y, a1.z * b1.z, a1.w * b1.w};

    float f[N_PERS];
    #pragma unroll
    for (int p = 0; p < N_PERS; p++) {
        const float* wp = mw + p * N_FEAT + 8 * lane;
        float t0 = 0.f;
        #pragma unroll
        for (int k = 0; k < 8; k++) {
            float w = __ldg(wp + k);
            t0 += pr[k] * w * w;
        }
        f[p] = t0;
    }
    #pragma unroll
    for (int p = 0; p < N_PERS; p++)
        #pragma unroll
        for (int o = 16; o > 0; o >>= 1)
            f[p] += __shfl_xor_sync(0xffffffffu, f[p], o);

    if (lane == 0) {
        float4 ri = g_rinv4[i];
        float4 rj = g_rinv4[j];
        float sim = 0.25f * (f[0] * ri.x * rj.x + f[1] * ri.y * rj.y
                           + f[2] * ri.z * rj.z + f[3] * ri.w * rj.w);
        if (sim > EPSILON) {
            size_t idx = (size_t)i * N_SEL + j;
            unsigned bit = 1u << (idx & 31u);
            int word = (int)(idx >> 5);
            unsigned old = atomicOr(&g_bitmap[word], bit);
            if (!(old & bit)) {
                int slot = atomicAdd(&g_nhits, 1);
                g_hit_off[slot]  = __ldg(smap + i) * N_TOTAL + __ldg(smap + j);
                g_hit_val[slot]  = sim * g_nodew[i];
                g_hit_word[slot] = word;
            }
        }
    }
}

// ---------------- main: interleaved zero-fill + bf16 edge screen ----------------
__global__ void __launch_bounds__(256, 4) main_kernel(const float* __restrict__ x,
                                                      const float* __restrict__ mw,
                                                      const int* __restrict__ fe,
                                                      const int* __restrict__ smap,
                                                      float4* __restrict__ out4) {
    int tidg = blockIdx.x * 256 + threadIdx.x;     // 0..NT-1
    int lane = threadIdx.x & 31;
    int warp = tidg >> 5;                          // 0..NWARP-1

    // fp32 squared weights for this lane's 8 dims, all 4 perspectives (32 regs)
    float w2[N_PERS][8];
    #pragma unroll
    for (int p = 0; p < N_PERS; p++)
        #pragma unroll
        for (int k = 0; k < 8; k++) {
            float w = __ldg(mw + p * N_FEAT + 8 * lane + k);
            w2[p][k] = w * w;
        }

    const float4 z = make_float4(0.f, 0.f, 0.f, 0.f);
    int fidx = tidg;

    for (int it = 0; it < MAIN_ITERS; it++) {
        // ---- two streaming zero-stores (hidden under edge load latency) ----
        if (fidx < OUT_F4) __stcs(out4 + fidx, z);
        int f2 = fidx + NT;
        if (f2 < OUT_F4) __stcs(out4 + f2, z);
        fidx += 2 * NT;

        // ---- one edge screen ----
        int e = warp + it * NWARP;
        if (e >= E_FULL) continue;
        int i = __ldg(fe + e);
        int j = __ldg(fe + E_FULL + e);

        uint4 qi = __ldg(g_qtab + i * 32 + lane);
        uint4 qj = __ldg(g_qtab + j * 32 + lane);

        float al, ah, bl, bh, pr[8];
        exp_bf2(qi.x, al, ah); exp_bf2(qj.x, bl, bh); pr[0] = al * bl; pr[1] = ah * bh;
        exp_bf2(qi.y, al, ah); exp_bf2(qj.y, bl, bh); pr[2] = al * bl; pr[3] = ah * bh;
        exp_bf2(qi.z, al, ah); exp_bf2(qj.z, bl, bh); pr[4] = al * bl; pr[5] = ah * bh;
        exp_bf2(qi.w, al, ah); exp_bf2(qj.w, bl, bh); pr[6] = al * bl; pr[7] = ah * bh;

        float f0 = 0.f, f1 = 0.f, f2v = 0.f, f3 = 0.f;
        #pragma unroll
        for (int k = 0; k < 8; k++) {
            f0 += pr[k] * w2[0][k];
            f1 += pr[k] * w2[1][k];
            f2v += pr[k] * w2[2][k];
            f3 += pr[k] * w2[3][k];
        }

        // 6-shuffle multi-value reduction -> lane class c=lane&3 holds total of acc_c
        bool o1 = lane & 1;
        float u0 = o1 ? f0 : f1;
        float v0 = (o1 ? f1 : f0) + __shfl_xor_sync(0xffffffffu, u0, 1);
        float u1 = o1 ? f2v : f3;
        float v1 = (o1 ? f3 : f2v) + __shfl_xor_sync(0xffffffffu, u1, 1);
        bool o2 = lane & 2;
        float tt = o2 ? v0 : v1;
        float w  = (o2 ? v1 : v0) + __shfl_xor_sync(0xffffffffu, tt, 2);
        w += __shfl_xor_sync(0xffffffffu, w, 4);
        w += __shfl_xor_sync(0xffffffffu, w, 8);
        w += __shfl_xor_sync(0xffffffffu, w, 16);

        int c = lane & 3;
        float ri = __ldg(reinterpret_cast<const float*>(g_rinv4) + 4 * i + c);
        float rj = __ldg(reinterpret_cast<const float*>(g_rinv4) + 4 * j + c);
        float s = w * ri * rj;
        s += __shfl_xor_sync(0xffffffffu, s, 1);
        s += __shfl_xor_sync(0xffffffffu, s, 2);
        float simA = 0.25f * __shfl_sync(0xffffffffu, s, 0);

        if (simA > SCREEN && i != j)
            exact_edge(i, j, lane, x, mw, smap);   // warp-uniform rare path
    }
}

// ---------------- scatter: raw edges + hits + lazy bitmap clear ----------------
__global__ void scatter_kernel(const int* __restrict__ re, float* __restrict__ out) {
    int t = blockIdx.x * blockDim.x + threadIdx.x;   // exactly E_RAW threads
    int r = __ldg(re + t);
    int c = __ldg(re + E_RAW + t);
    atomicAdd(out + (size_t)r * N_TOTAL + c, 1.0f - LAMB1);
    if (t < g_nhits) {
        atomicAdd(out + (size_t)g_hit_off[t], g_hit_val[t]);
        g_bitmap[g_hit_word[t]] = 0;                 // keep replay-deterministic
    }
}

// ---------------- launch ----------------
extern "C" void kernel_launch(void* const* d_in, const int* in_sizes, int n_in,
                              void* d_out, int out_size) {
    const float* x      = (const float*)d_in[0];   // [8192, 256]
    const float* mw     = (const float*)d_in[1];   // [4, 256]
    const int*   batch  = (const int*)  d_in[2];   // [8192]
    const int*   smap   = (const int*)  d_in[3];   // [8192]
    const int*   belong = (const int*)  d_in[4];   // [256]
    const float* score  = (const float*)d_in[5];   // [256]
    const int*   fe     = (const int*)  d_in[6];   // [2, 262144]
    const int*   re     = (const int*)  d_in[7];   // [2, 262144]
    float* out = (float*)d_out;                    // [8192, 8192]

    prep_kernel<<<1025, 256>>>(x, mw, score, belong, batch);
    main_kernel<<<MAIN_BLOCKS, 256>>>(x, mw, fe, smap,
                                      reinterpret_cast<float4*>(out));
    scatter_kernel<<<E_RAW / 256, 256>>>(re, out);
}

// round 6
// speedup vs baseline: 2.5302x; 1.3084x over previous
#include <cuda_runtime.h>
#include <cuda_fp16.h>
#include <cuda_fp8.h>

#define N_SEL   8192
#define N_FEAT  256
#define K_SUB   256
#define N_PERS  4
#define E_FULL  262144
#define E_RAW   262144
#define N_TOTAL 8192
#define EPSILON 0.5f
#define SCREEN  0.35f
#define LAMB1   0.5f

#define MAIN_BLOCKS 592                 // 4 per SM * 148 SMs (fully resident)
#define NT          (MAIN_BLOCKS * 256) // 151552 threads
#define NWARP       (NT / 32)           // 4736 warps
#define MAIN_ITERS  56                  // 56*2*NT >= 16777216 ; 56*NWARP >= E_FULL
#define OUT_F4      16777216            // 8192*8192/4

// ---------------- device scratch (no device allocations allowed) ----------------
__device__ uint2    g_qtab[N_SEL * 32];   // fp8 e4m3 table: 256 B/row (2 MB)
__device__ float4   g_rinv4[N_SEL];       // per-node {rinv_p0..p3}
__device__ float    g_nodew[N_SEL];       // score[batch[i]] * LAMB1
__device__ unsigned g_bitmap[(size_t)N_SEL * N_SEL / 32];  // dedup, lazily cleared
__device__ int      g_nhits;
__device__ int      g_hit_off[E_FULL];
__device__ float    g_hit_val[E_FULL];
__device__ int      g_hit_word[E_FULL];

// ---------------- helpers ----------------
__device__ __forceinline__ unsigned short f2_to_fp8x2(float a, float b) {
    float2 v = make_float2(a, b);
    return __nv_cvt_float2_to_fp8x2(v, __NV_SATFINITE, __NV_E4M3);
}
__device__ __forceinline__ __half2 fp8x2_to_h2(unsigned short u) {
    __half2_raw r = __nv_cvt_fp8x2_to_halfraw2((__nv_fp8x2_storage_t)u, __NV_E4M3);
    return *reinterpret_cast<__half2*>(&r);
}

// ---------------- prep: quant + rinv (blocks 0..1023) | score/nodew (block 1024) ----
__global__ void __launch_bounds__(256) prep_kernel(const float* __restrict__ x,
                                                   const float* __restrict__ mw,
                                                   const float* __restrict__ sc,
                                                   const int* __restrict__ belong,
                                                   const int* __restrict__ batch) {
    if (blockIdx.x == 1024) {
        __shared__ float s_sc[K_SUB];
        __shared__ int   s_bl[K_SUB];
        __shared__ float s_sum[K_SUB];
        __shared__ float s_norm[K_SUB];
        int t = threadIdx.x;
        s_sc[t] = sc[t];
        s_bl[t] = belong[t];
        __syncthreads();
        float s = 0.f;
        #pragma unroll 8
        for (int k = 0; k < K_SUB; k++)
            s += (s_bl[k] == t) ? s_sc[k] : 0.f;
        s_sum[t] = s;
        __syncthreads();
        s_norm[t] = s_sc[t] / s_sum[s_bl[t]];
        if (t == 0) g_nhits = 0;
        __syncthreads();
        for (int i = t; i < N_SEL; i += K_SUB)
            g_nodew[i] = s_norm[batch[i]] * LAMB1;
        return;
    }

    // ---- per-node (warp per node): fp8 quant + 4 inverse weighted norms ----
    int lane = threadIdx.x & 31;
    int n = (blockIdx.x * blockDim.x + threadIdx.x) >> 5;

    // lane owns dims [8*lane, 8*lane+8)
    const float4* xr = reinterpret_cast<const float4*>(x + (size_t)n * N_FEAT);
    float4 a = __ldg(xr + 2 * lane);
    float4 b = __ldg(xr + 2 * lane + 1);

    unsigned lo = (unsigned)f2_to_fp8x2(a.x, a.y) | ((unsigned)f2_to_fp8x2(a.z, a.w) << 16);
    unsigned hi = (unsigned)f2_to_fp8x2(b.x, b.y) | ((unsigned)f2_to_fp8x2(b.z, b.w) << 16);
    g_qtab[n * 32 + lane] = make_uint2(lo, hi);

    float sq[8] = {a.x * a.x, a.y * a.y, a.z * a.z, a.w * a.w,
                   b.x * b.x, b.y * b.y, b.z * b.z, b.w * b.w};

    const float4* mw4 = reinterpret_cast<const float4*>(mw);
    float acc[N_PERS];
    #pragma unroll
    for (int p = 0; p < N_PERS; p++) {
        float4 wa = __ldg(mw4 + p * 64 + 2 * lane);
        float4 wb = __ldg(mw4 + p * 64 + 2 * lane + 1);
        acc[p] = sq[0] * wa.x * wa.x + sq[1] * wa.y * wa.y
               + sq[2] * wa.z * wa.z + sq[3] * wa.w * wa.w
               + sq[4] * wb.x * wb.x + sq[5] * wb.y * wb.y
               + sq[6] * wb.z * wb.z + sq[7] * wb.w * wb.w;
    }
    #pragma unroll
    for (int p = 0; p < N_PERS; p++)
        #pragma unroll
        for (int o = 16; o > 0; o >>= 1)
            acc[p] += __shfl_xor_sync(0xffffffffu, acc[p], o);

    if (lane == 0)
        g_rinv4[n] = make_float4(1.0f / (sqrtf(acc[0]) + 1e-12f),
                                 1.0f / (sqrtf(acc[1]) + 1e-12f),
                                 1.0f / (sqrtf(acc[2]) + 1e-12f),
                                 1.0f / (sqrtf(acc[3]) + 1e-12f));
}

// ---------------- rare exact path: fp32 recompute + dedup + hit record ----------------
__device__ __noinline__ void exact_edge(int i, int j, int lane,
                                        const float* __restrict__ x,
                                        const float* __restrict__ mw,
                                        const int* __restrict__ smap) {
    const float4* xi = reinterpret_cast<const float4*>(x + (size_t)i * N_FEAT);
    const float4* xj = reinterpret_cast<const float4*>(x + (size_t)j * N_FEAT);
    float4 a0 = __ldg(xi + 2 * lane), a1 = __ldg(xi + 2 * lane + 1);
    float4 b0 = __ldg(xj + 2 * lane), b1 = __ldg(xj + 2 * lane + 1);
    float pr[8] = {a0.x * b0.x, a0.y * b0.y, a0.z * b0.z, a0.w * b0.w,
                   a1.x * b1.x, a1.y * b1.y, a1.z * b1.z, a1.w * b1.w};

    const float4* mw4 = reinterpret_cast<const float4*>(mw);
    float f[N_PERS];
    #pragma unroll
    for (int p = 0; p < N_PERS; p++) {
        float4 wa = __ldg(mw4 + p * 64 + 2 * lane);
        float4 wb = __ldg(mw4 + p * 64 + 2 * lane + 1);
        f[p] = pr[0] * wa.x * wa.x + pr[1] * wa.y * wa.y
             + pr[2] * wa.z * wa.z + pr[3] * wa.w * wa.w
             + pr[4] * wb.x * wb.x + pr[5] * wb.y * wb.y
             + pr[6] * wb.z * wb.z + pr[7] * wb.w * wb.w;
    }
    #pragma unroll
    for (int p = 0; p < N_PERS; p++)
        #pragma unroll
        for (int o = 16; o > 0; o >>= 1)
            f[p] += __shfl_xor_sync(0xffffffffu, f[p], o);

    if (lane == 0) {
        float4 ri = g_rinv4[i];
        float4 rj = g_rinv4[j];
        float sim = 0.25f * (f[0] * ri.x * rj.x + f[1] * ri.y * rj.y
                           + f[2] * ri.z * rj.z + f[3] * ri.w * rj.w);
        if (sim > EPSILON) {
            size_t idx = (size_t)i * N_SEL + j;
            unsigned bit = 1u << (idx & 31u);
            int word = (int)(idx >> 5);
            unsigned old = atomicOr(&g_bitmap[word], bit);
            if (!(old & bit)) {
                int slot = atomicAdd(&g_nhits, 1);
                g_hit_off[slot]  = __ldg(smap + i) * N_TOTAL + __ldg(smap + j);
                g_hit_val[slot]  = sim * g_nodew[i];
                g_hit_word[slot] = word;
            }
        }
    }
}

// ---------------- main: interleaved zero-fill + fp8 edge screen ----------------
__global__ void __launch_bounds__(256, 4) main_kernel(const float* __restrict__ x,
                                                      const float* __restrict__ mw,
                                                      const int* __restrict__ fe,
                                                      const int* __restrict__ smap,
                                                      float4* __restrict__ out4) {
    int tidg = blockIdx.x * 256 + threadIdx.x;     // 0..NT-1
    int lane = threadIdx.x & 31;
    int warp = tidg >> 5;                          // 0..NWARP-1

    // squared weights in half2, lane's 8 dims x 4 perspectives (16 regs)
    __half2 w2r[N_PERS][4];
    {
        const float4* mw4 = reinterpret_cast<const float4*>(mw);
        #pragma unroll
        for (int p = 0; p < N_PERS; p++) {
            float4 wa = __ldg(mw4 + p * 64 + 2 * lane);
            float4 wb = __ldg(mw4 + p * 64 + 2 * lane + 1);
            w2r[p][0] = __floats2half2_rn(wa.x * wa.x, wa.y * wa.y);
            w2r[p][1] = __floats2half2_rn(wa.z * wa.z, wa.w * wa.w);
            w2r[p][2] = __floats2half2_rn(wb.x * wb.x, wb.y * wb.y);
            w2r[p][3] = __floats2half2_rn(wb.z * wb.z, wb.w * wb.w);
        }
    }

    const float4 z = make_float4(0.f, 0.f, 0.f, 0.f);
    int fidx = tidg;

    // pipeline: preload iteration-0 edge indices
    int e0 = warp;
    int i_n = (e0 < E_FULL) ? __ldg(fe + e0) : 0;
    int j_n = (e0 < E_FULL) ? __ldg(fe + E_FULL + e0) : 0;

    for (int it = 0; it < MAIN_ITERS; it++) {
        // ---- two streaming zero-stores (hidden under edge load latency) ----
        if (fidx < OUT_F4) __stcs(out4 + fidx, z);
        int f2i = fidx + NT;
        if (f2i < OUT_F4) __stcs(out4 + f2i, z);
        fidx += 2 * NT;

        int e = warp + it * NWARP;
        if (e >= E_FULL) continue;
        int i = i_n, j = j_n;

        // kick off this edge's table loads first (longest chain)
        uint2 qi = __ldg(g_qtab + i * 32 + lane);
        uint2 qj = __ldg(g_qtab + j * 32 + lane);

        // prefetch next iteration's indices (breaks fe->qtab serial chain)
        int en = e + NWARP;
        if (en < E_FULL) {
            i_n = __ldg(fe + en);
            j_n = __ldg(fe + E_FULL + en);
        }

        // hw fp8x2 -> half2 decode (8 cvts)
        __half2 hi0 = fp8x2_to_h2((unsigned short)(qi.x & 0xffffu));
        __half2 hi1 = fp8x2_to_h2((unsigned short)(qi.x >> 16));
        __half2 hi2 = fp8x2_to_h2((unsigned short)(qi.y & 0xffffu));
        __half2 hi3 = fp8x2_to_h2((unsigned short)(qi.y >> 16));
        __half2 hj0 = fp8x2_to_h2((unsigned short)(qj.x & 0xffffu));
        __half2 hj1 = fp8x2_to_h2((unsigned short)(qj.x >> 16));
        __half2 hj2 = fp8x2_to_h2((unsigned short)(qj.y & 0xffffu));
        __half2 hj3 = fp8x2_to_h2((unsigned short)(qj.y >> 16));

        __half2 pr0 = __hmul2(hi0, hj0);
        __half2 pr1 = __hmul2(hi1, hj1);
        __half2 pr2 = __hmul2(hi2, hj2);
        __half2 pr3 = __hmul2(hi3, hj3);

        __half2 a0 = __hmul2(pr0, w2r[0][0]);
        __half2 a1 = __hmul2(pr0, w2r[1][0]);
        __half2 a2 = __hmul2(pr0, w2r[2][0]);
        __half2 a3 = __hmul2(pr0, w2r[3][0]);
        a0 = __hfma2(pr1, w2r[0][1], a0); a1 = __hfma2(pr1, w2r[1][1], a1);
        a2 = __hfma2(pr1, w2r[2][1], a2); a3 = __hfma2(pr1, w2r[3][1], a3);
        a0 = __hfma2(pr2, w2r[0][2], a0); a1 = __hfma2(pr2, w2r[1][2], a1);
        a2 = __hfma2(pr2, w2r[2][2], a2); a3 = __hfma2(pr2, w2r[3][2], a3);
        a0 = __hfma2(pr3, w2r[0][3], a0); a1 = __hfma2(pr3, w2r[1][3], a1);
        a2 = __hfma2(pr3, w2r[2][3], a2); a3 = __hfma2(pr3, w2r[3][3], a3);

        float f0 = __low2float(a0) + __high2float(a0);
        float f1 = __low2float(a1) + __high2float(a1);
        float f2 = __low2float(a2) + __high2float(a2);
        float f3 = __low2float(a3) + __high2float(a3);

        // 6-shuffle multi-value reduction -> lane class c=lane&3 holds total of acc_c
        bool o1 = lane & 1;
        float u0 = o1 ? f0 : f1;
        float v0 = (o1 ? f1 : f0) + __shfl_xor_sync(0xffffffffu, u0, 1);
        float u1 = o1 ? f2 : f3;
        float v1 = (o1 ? f3 : f2) + __shfl_xor_sync(0xffffffffu, u1, 1);
        bool o2 = lane & 2;
        float tt = o2 ? v0 : v1;
        float w  = (o2 ? v1 : v0) + __shfl_xor_sync(0xffffffffu, tt, 2);
        w += __shfl_xor_sync(0xffffffffu, w, 4);
        w += __shfl_xor_sync(0xffffffffu, w, 8);
        w += __shfl_xor_sync(0xffffffffu, w, 16);

        int c = lane & 3;
        float ri = __ldg(reinterpret_cast<const float*>(g_rinv4) + 4 * i + c);
        float rj = __ldg(reinterpret_cast<const float*>(g_rinv4) + 4 * j + c);
        float s = w * ri * rj;
        s += __shfl_xor_sync(0xffffffffu, s, 1);
        s += __shfl_xor_sync(0xffffffffu, s, 2);
        float simA = 0.25f * __shfl_sync(0xffffffffu, s, 0);

        if (simA > SCREEN && i != j)
            exact_edge(i, j, lane, x, mw, smap);   // warp-uniform rare path
    }
}

// ---------------- scatter: raw edges + hits + lazy bitmap clear ----------------
__global__ void scatter_kernel(const int* __restrict__ re, float* __restrict__ out) {
    int t = blockIdx.x * blockDim.x + threadIdx.x;   // exactly E_RAW threads
    int r = __ldg(re + t);
    int c = __ldg(re + E_RAW + t);
    atomicAdd(out + (size_t)r * N_TOTAL + c, 1.0f - LAMB1);
    if (t < g_nhits) {
        atomicAdd(out + (size_t)g_hit_off[t], g_hit_val[t]);
        g_bitmap[g_hit_word[t]] = 0;                 // keep replay-deterministic
    }
}

// ---------------- launch ----------------
extern "C" void kernel_launch(void* const* d_in, const int* in_sizes, int n_in,
                              void* d_out, int out_size) {
    const float* x      = (const float*)d_in[0];   // [8192, 256]
    const float* mw     = (const float*)d_in[1];   // [4, 256]
    const int*   batch  = (const int*)  d_in[2];   // [8192]
    const int*   smap   = (const int*)  d_in[3];   // [8192]
    const int*   belong = (const int*)  d_in[4];   // [256]
    const float* score  = (const float*)d_in[5];   // [256]
    const int*   fe     = (const int*)  d_in[6];   // [2, 262144]
    const int*   re     = (const int*)  d_in[7];   // [2, 262144]
    float* out = (float*)d_out;                    // [8192, 8192]

    prep_kernel<<<1025, 256>>>(x, mw, score, belong, batch);
    main_kernel<<<MAIN_BLOCKS, 256>>>(x, mw, fe, smap,
                                      reinterpret_cast<float4*>(out));
    scatter_kernel<<<E_RAW / 256, 256>>>(re, out);
}